// round 6
// baseline (speedup 1.0000x reference)
#include <cuda_runtime.h>
#include <cuda_bf16.h>
#include <math.h>
#include <stdint.h>

#ifndef M_PI
#define M_PI 3.14159265358979323846
#endif

#define Bc 256
#define Lc 256
#define Dc 128
#define Hc 2
#define Ec 64
#define NLc 2
#define TOPKc 5
#define NUM_TOTAL_C 100000
#define INV_SQRT_E 0.125f
#define INV_SQRT_2F 0.70710678118654752440f

typedef __nv_bfloat16 bf16;

// ---------------- scratch ----------------
__device__ float g_x  [Bc*Lc*Dc];
__device__ float g_mask[Bc*Lc];
__device__ float g_vb [Bc*Lc*Dc];
__device__ float g_sp [Bc*Lc*Dc];
__device__ float g_mv [Bc*Lc];
__device__ float g_mvp[8*Bc*Lc];
__device__ float g_gm [Lc];
__device__ int   g_delays[TOPKc];
__device__ float g_w  [Bc*TOPKc];
__device__ float g_c  [Lc];

__device__ bf16 g_Cm3 [Lc*3*Lc];
__device__ bf16 g_xA3 [Bc*Lc*3*Dc];
__device__ bf16 g_xB3 [(size_t)Bc*3*Lc*Dc];
__device__ bf16 g_xtA3[Bc*Lc*3*Dc];
__device__ bf16 g_qt3 [Bc*Lc*3*Dc];
__device__ bf16 g_kt3 [Bc*Lc*3*Dc];
__device__ bf16 g_vth [Bc*Lc*Dc];
__device__ bf16 g_vtl [Bc*Lc*Dc];
__device__ bf16 g_o3  [Bc*Lc*3*Dc];
__device__ bf16 g_a3  [Bc*Lc*3*Dc];
__device__ bf16 g_h3  [(size_t)Bc*Lc*3*2*Dc];
__device__ bf16 g_W3  [6*3*Dc*2*Dc];

#define W3_Q  0
#define W3_K  (3*Dc*Dc)
#define W3_V  (2*3*Dc*Dc)
#define W3_P  (3*3*Dc*Dc)
#define W3_F1 (4*3*Dc*Dc)
#define W3_F2 (4*3*Dc*Dc + 3*Dc*2*Dc)

// ---------------- PTX helpers ----------------
__device__ __forceinline__ uint32_t smem_u32(const void* p) {
    return (uint32_t)__cvta_generic_to_shared(p);
}
__device__ __forceinline__ void cpasync16(void* sp, const void* gp) {
    asm volatile("cp.async.cg.shared.global [%0], [%1], 16;"
                 :: "r"(smem_u32(sp)), "l"(gp));
}
#define CP_COMMIT() asm volatile("cp.async.commit_group;")
#define CP_WAIT0()  asm volatile("cp.async.wait_group 0;")

#define LDSM_X4(r0,r1,r2,r3,addr) \
    asm volatile("ldmatrix.sync.aligned.m8n8.x4.shared.b16 {%0,%1,%2,%3}, [%4];" \
        : "=r"(r0),"=r"(r1),"=r"(r2),"=r"(r3) : "r"(addr))
#define LDSM_X4_T(r0,r1,r2,r3,addr) \
    asm volatile("ldmatrix.sync.aligned.m8n8.x4.trans.shared.b16 {%0,%1,%2,%3}, [%4];" \
        : "=r"(r0),"=r"(r1),"=r"(r2),"=r"(r3) : "r"(addr))

#define MMA_BF16(d, a, b0v, b1v) \
    asm volatile("mma.sync.aligned.m16n8k16.row.col.f32.bf16.bf16.f32 " \
        "{%0,%1,%2,%3}, {%4,%5,%6,%7}, {%8,%9}, {%0,%1,%2,%3};" \
        : "+f"(d[0]), "+f"(d[1]), "+f"(d[2]), "+f"(d[3]) \
        : "r"(a[0]), "r"(a[1]), "r"(a[2]), "r"(a[3]), "r"(b0v), "r"(b1v))

// ---------------- bf16x3 tensor-core GEMM with emit epilogue ----------------
// C = A3 @ B3 (NN, K tripled). emit bits: 1=fp32 C, 2=A-role triple(h,h,l)->aux1,
// 4=B-transB triple(h,l,h)->aux1, 8=h->aux1,l->aux2, 16=row-triple(h,l,h)->aux2.
// fuse: 0 none, 1 +=R, 2 exact-erf GELU.
template<int BN>
__global__ __launch_bounds__(256, 2)
void mma_kernel(const bf16* __restrict__ A, const bf16* __restrict__ Bp,
                float* __restrict__ C,
                int K, int lda, int ldb, int ldc,
                int zdiv, long sA1, long sA2, long sB1, long sB2, long sC1, long sC2,
                const float* __restrict__ R, int ldr, int fuse,
                int emit, bf16* __restrict__ aux1, bf16* __restrict__ aux2)
{
    constexpr int MT   = 4;    // warp M tile 64
    constexpr int NT16 = 2;    // warp N tile 32
    constexpr int BK   = 32;

    const int tid  = threadIdx.x;
    const int warp = tid >> 5;
    const int lane = tid & 31;
    const int warpM0 = (warp & 1) * 64;
    const int warpN0 = (warp >> 1) * 32;

    int z = blockIdx.z, z1 = z / zdiv, z2 = z - z1 * zdiv;
    long coff = z1 * sC1 + z2 * sC2;
    A  += z1 * sA1 + z2 * sA2;
    Bp += z1 * sB1 + z2 * sB2;
    C  += coff;
    if (aux1) aux1 += 3 * coff;
    if (aux2) aux2 += 3 * coff;

    const int m0 = blockIdx.x * 128;
    const int n0 = blockIdx.y * BN;

    __shared__ bf16 As[2][128][BK + 8];
    __shared__ bf16 Bs[2][BK][BN + 8];

    auto load_tiles = [&](int buf, int k0) {
        #pragma unroll
        for (int i = 0; i < 2; i++) {
            int c = tid + i * 256;
            int row = c >> 2, kc = (c & 3) << 3;
            cpasync16(&As[buf][row][kc], A + (size_t)(m0 + row) * lda + k0 + kc);
        }
        constexpr int CPR = BN / 8;
        constexpr int BCH = 32 * CPR;
        #pragma unroll
        for (int i = 0; i < BCH / 256; i++) {
            int c = tid + i * 256;
            int row = c / CPR, nc = (c % CPR) << 3;
            cpasync16(&Bs[buf][row][nc], Bp + (size_t)(k0 + row) * ldb + n0 + nc);
        }
    };

    float acc[MT][NT16][2][4];
    #pragma unroll
    for (int i = 0; i < MT; i++)
        #pragma unroll
        for (int j = 0; j < NT16; j++)
            #pragma unroll
            for (int s = 0; s < 2; s++)
                #pragma unroll
                for (int q = 0; q < 4; q++) acc[i][j][s][q] = 0.f;

    const int nk = K / BK;
    load_tiles(0, 0);
    CP_COMMIT();

    int buf = 0;
    for (int kt = 0; kt < nk; kt++) {
        CP_WAIT0();
        __syncthreads();
        if (kt + 1 < nk) { load_tiles(buf ^ 1, (kt + 1) * BK); CP_COMMIT(); }
        #pragma unroll
        for (int ks = 0; ks < 2; ks++) {
            uint32_t a[MT][4];
            #pragma unroll
            for (int tm = 0; tm < MT; tm++) {
                uint32_t addr = smem_u32(
                    &As[buf][warpM0 + tm*16 + (lane & 15)][ks*16 + ((lane >> 4) << 3)]);
                LDSM_X4(a[tm][0], a[tm][1], a[tm][2], a[tm][3], addr);
            }
            uint32_t b[NT16][4];
            #pragma unroll
            for (int tn = 0; tn < NT16; tn++) {
                uint32_t addr = smem_u32(
                    &Bs[buf][ks*16 + (lane & 15)][warpN0 + tn*16 + ((lane >> 4) << 3)]);
                LDSM_X4_T(b[tn][0], b[tn][1], b[tn][2], b[tn][3], addr);
            }
            #pragma unroll
            for (int tm = 0; tm < MT; tm++)
                #pragma unroll
                for (int tn = 0; tn < NT16; tn++) {
                    MMA_BF16(acc[tm][tn][0], a[tm], b[tn][0], b[tn][1]);
                    MMA_BF16(acc[tm][tn][1], a[tm], b[tn][2], b[tn][3]);
                }
        }
        buf ^= 1;
    }

    #pragma unroll
    for (int tm = 0; tm < MT; tm++)
        #pragma unroll
        for (int tn = 0; tn < NT16; tn++)
            #pragma unroll
            for (int s = 0; s < 2; s++) {
                int col = n0 + warpN0 + tn*16 + s*8 + ((lane & 3) << 1);
                float* cc = acc[tm][tn][s];
                #pragma unroll
                for (int hr = 0; hr < 2; hr++) {
                    int row = m0 + warpM0 + tm*16 + (lane >> 2) + hr*8;
                    float2 v = make_float2(cc[hr*2 + 0], cc[hr*2 + 1]);
                    if (fuse == 1) {
                        float2 r = *(const float2*)&R[(size_t)row * ldr + col];
                        v.x += r.x; v.y += r.y;
                    } else if (fuse == 2) {
                        v.x = v.x * 0.5f * (1.0f + erff(v.x * INV_SQRT_2F));
                        v.y = v.y * 0.5f * (1.0f + erff(v.y * INV_SQRT_2F));
                    }
                    size_t ci = (size_t)row * ldc + col;
                    if (emit & 1) *(float2*)&C[ci] = v;
                    if (emit & 0x1E) {
                        bf16 hx = __float2bfloat16(v.x);
                        bf16 lx = __float2bfloat16(v.x - __bfloat162float(hx));
                        bf16 hy = __float2bfloat16(v.y);
                        bf16 ly = __float2bfloat16(v.y - __bfloat162float(hy));
                        if (emit & 2) {
                            bf16* o = aux1 + (size_t)row * (3*ldc) + 3*col;
                            o[0]=hx; o[1]=hx; o[2]=lx; o[3]=hy; o[4]=hy; o[5]=ly;
                        }
                        if (emit & 4) {
                            bf16* o = aux1 + (size_t)row * (3*ldc) + 3*col;
                            o[0]=hx; o[1]=lx; o[2]=hx; o[3]=hy; o[4]=ly; o[5]=hy;
                        }
                        if (emit & 8) {
                            aux1[ci] = hx; aux1[ci+1] = hy;
                            aux2[ci] = lx; aux2[ci+1] = ly;
                        }
                        if (emit & 16) {
                            bf16* o = aux2 + (size_t)(3*row) * ldc + col;
                            o[0] = hx;        o[1] = hy;
                            o[ldc] = lx;      o[ldc+1] = ly;
                            o[2*ldc] = hx;    o[2*ldc+1] = hy;
                        }
                    }
                }
            }
}

// ---------------- fused attention ----------------
// One block = (q-tile of 64, b, h). Computes raw S, meanv partials, softmax,
// and O = P@V (3-chain split) entirely on-chip.
__global__ __launch_bounds__(256, 1)
void fattn_kernel(const bf16* __restrict__ qt3, const bf16* __restrict__ kt3,
                  const bf16* __restrict__ vth, const bf16* __restrict__ vtl,
                  const float* __restrict__ maskg,
                  float* __restrict__ sp, float* __restrict__ mvp)
{
    extern __shared__ char sm[];
    bf16*  Vh = (bf16*) (sm + 0);          // [256][72]
    bf16*  Vl = (bf16*) (sm + 36864);      // [256][72]
    bf16*  Q3 = (bf16*) (sm + 73728);      // [64][200]   (phase-1 only)
    bf16*  K3 = (bf16*) (sm + 99328);      // [256][200]  (phase-1 only)
    float* Ss = (float*)(sm + 73728);      // [64][264]   (phase-2, overlays Q3/K3)
    bf16*  Ph = (bf16*) (sm + 141312);     // [64][264]
    bf16*  Pl = (bf16*) (sm + 175104);     // [64][264]
    float* mk = (float*)(sm + 208896);     // [256]

    const int tid = threadIdx.x, warp = tid >> 5, lane = tid & 31;
    const int q0 = blockIdx.x * 64;
    const int b  = blockIdx.y >> 1, h = blockIdx.y & 1;

    // prologue: load everything
    const bf16* qg = qt3 + ((size_t)(b*Lc + q0)) * 384 + h*192;
    for (int c = tid; c < 1536; c += 256) {
        int r = c / 24, kc = (c % 24) * 8;
        cpasync16(&Q3[r*200 + kc], qg + (size_t)r*384 + kc);
    }
    const bf16* kg = kt3 + ((size_t)(b*Lc)) * 384 + h*192;
    for (int c = tid; c < 6144; c += 256) {
        int r = c / 24, kc = (c % 24) * 8;
        cpasync16(&K3[r*200 + kc], kg + (size_t)r*384 + kc);
    }
    const bf16* vhg = vth + ((size_t)(b*Lc)) * Dc + h*64;
    const bf16* vlg = vtl + ((size_t)(b*Lc)) * Dc + h*64;
    for (int c = tid; c < 2048; c += 256) {
        int r = c >> 3, e = (c & 7) * 8;
        cpasync16(&Vh[r*72 + e], vhg + (size_t)r*Dc + e);
        cpasync16(&Vl[r*72 + e], vlg + (size_t)r*Dc + e);
    }
    for (int c = tid; c < 64; c += 256)
        cpasync16(&mk[c*4], maskg + b*Lc + c*4);
    CP_COMMIT(); CP_WAIT0();
    __syncthreads();

    // phase 1: S = Q3 @ K3^T   (M=64, N=256 keys, K=192)
    const int wM = (warp & 1) * 32;
    const int wN = (warp >> 1) * 64;
    float accS[2][4][2][4];
    #pragma unroll
    for (int i=0;i<2;i++) for (int j=0;j<4;j++) for (int s=0;s<2;s++)
        for (int q=0;q<4;q++) accS[i][j][s][q] = 0.f;

    for (int kf = 0; kf < 12; kf++) {
        uint32_t a[2][4], bb[4][4];
        #pragma unroll
        for (int mf = 0; mf < 2; mf++) {
            uint32_t addr = smem_u32(&Q3[(wM + mf*16 + (lane & 15))*200
                                         + kf*16 + ((lane >> 4) << 3)]);
            LDSM_X4(a[mf][0], a[mf][1], a[mf][2], a[mf][3], addr);
        }
        #pragma unroll
        for (int tn = 0; tn < 4; tn++) {
            uint32_t addr = smem_u32(&K3[(wN + tn*16 + (lane & 15))*200
                                         + kf*16 + ((lane >> 4) << 3)]);
            LDSM_X4(bb[tn][0], bb[tn][1], bb[tn][2], bb[tn][3], addr);
        }
        #pragma unroll
        for (int mf = 0; mf < 2; mf++)
            #pragma unroll
            for (int tn = 0; tn < 4; tn++) {
                MMA_BF16(accS[mf][tn][0], a[mf], bb[tn][0], bb[tn][2]);
                MMA_BF16(accS[mf][tn][1], a[mf], bb[tn][1], bb[tn][3]);
            }
    }
    __syncthreads();   // done reading Q3/K3 before Ss overlays them

    #pragma unroll
    for (int mf = 0; mf < 2; mf++)
        #pragma unroll
        for (int tn = 0; tn < 4; tn++)
            #pragma unroll
            for (int s = 0; s < 2; s++)
                #pragma unroll
                for (int hr = 0; hr < 2; hr++) {
                    int row = wM + mf*16 + (lane >> 2) + hr*8;
                    int col = wN + tn*16 + s*8 + ((lane & 3) << 1);
                    *(float2*)&Ss[row*264 + col] =
                        make_float2(accS[mf][tn][s][hr*2], accS[mf][tn][s][hr*2+1]);
                }
    __syncthreads();

    // meanv partial: bin d gets sum over rows m of S[m][(q0+m-d) & 255]
    {
        int d = tid;
        float s = 0.f;
        #pragma unroll 8
        for (int m = 0; m < 64; m++)
            s += Ss[m*264 + ((q0 + m - d) & 255)];
        mvp[((size_t)(blockIdx.x*2 + h) * Bc + b) * Lc + d] = s * (1.0f/128.0f);
    }
    __syncthreads();

    // softmax (rows owned by thread quads), write Ph/Pl split
    {
        int row = tid >> 2, part = tid & 3;
        float* Sr = &Ss[row*264 + part*64];
        const float* mr = &mk[part*64];
        float mx = -1e30f;
        #pragma unroll 8
        for (int j = 0; j < 64; j++)
            mx = fmaxf(mx, Sr[j] * INV_SQRT_E + mr[j]);
        mx = fmaxf(mx, __shfl_xor_sync(0xffffffffu, mx, 1));
        mx = fmaxf(mx, __shfl_xor_sync(0xffffffffu, mx, 2));
        float sum = 0.f;
        #pragma unroll 8
        for (int j = 0; j < 64; j++) {
            float e = expf(Sr[j] * INV_SQRT_E + mr[j] - mx);
            Sr[j] = e; sum += e;
        }
        sum += __shfl_xor_sync(0xffffffffu, sum, 1);
        sum += __shfl_xor_sync(0xffffffffu, sum, 2);
        float inv = 1.0f / sum;
        bf16* ph = &Ph[row*264 + part*64];
        bf16* pl = &Pl[row*264 + part*64];
        #pragma unroll 8
        for (int j = 0; j < 64; j++) {
            float p = Sr[j] * inv;
            bf16 hh = __float2bfloat16(p);
            ph[j] = hh;
            pl[j] = __float2bfloat16(p - __bfloat162float(hh));
        }
    }
    __syncthreads();

    // phase 2: O = Ph@Vh + Ph@Vl + Pl@Vh   (M=64, N=64, K=256)
    const int wM2 = (warp & 1) * 32;
    const int wN2 = (warp >> 1) * 16;
    float o[2][2][4];
    #pragma unroll
    for (int i=0;i<2;i++) for (int s=0;s<2;s++) for (int q=0;q<4;q++) o[i][s][q]=0.f;

    for (int kf = 0; kf < 16; kf++) {
        uint32_t ah[2][4], al[2][4], bh[4], bl[4];
        #pragma unroll
        for (int mf = 0; mf < 2; mf++) {
            uint32_t r_off = (wM2 + mf*16 + (lane & 15))*264 + kf*16 + ((lane >> 4) << 3);
            LDSM_X4(ah[mf][0], ah[mf][1], ah[mf][2], ah[mf][3], smem_u32(&Ph[r_off]));
            LDSM_X4(al[mf][0], al[mf][1], al[mf][2], al[mf][3], smem_u32(&Pl[r_off]));
        }
        {
            uint32_t v_off = (kf*16 + (lane & 15))*72 + wN2 + ((lane >> 4) << 3);
            LDSM_X4_T(bh[0], bh[1], bh[2], bh[3], smem_u32(&Vh[v_off]));
            LDSM_X4_T(bl[0], bl[1], bl[2], bl[3], smem_u32(&Vl[v_off]));
        }
        #pragma unroll
        for (int mf = 0; mf < 2; mf++) {
            MMA_BF16(o[mf][0], ah[mf], bh[0], bh[1]);
            MMA_BF16(o[mf][1], ah[mf], bh[2], bh[3]);
            MMA_BF16(o[mf][0], ah[mf], bl[0], bl[1]);
            MMA_BF16(o[mf][1], ah[mf], bl[2], bl[3]);
            MMA_BF16(o[mf][0], al[mf], bh[0], bh[1]);
            MMA_BF16(o[mf][1], al[mf], bh[2], bh[3]);
        }
    }
    #pragma unroll
    for (int mf = 0; mf < 2; mf++)
        #pragma unroll
        for (int s = 0; s < 2; s++)
            #pragma unroll
            for (int hr = 0; hr < 2; hr++) {
                int row = q0 + wM2 + mf*16 + (lane >> 2) + hr*8;
                int col = h*64 + wN2 + s*8 + ((lane & 3) << 1);
                *(float2*)&sp[((size_t)b*Lc + row)*Dc + col] =
                    make_float2(o[mf][s][hr*2], o[mf][s][hr*2+1]);
            }
}

// ---------------- small kernels ----------------
__global__ void build_x_kernel(const int* __restrict__ paths,
                               const float* __restrict__ ego,
                               const float* __restrict__ pos)
{
    int bl = blockIdx.x, c = threadIdx.x;
    int p = paths[bl], l = bl & (Lc - 1);
    float v = ego[(size_t)p * Dc + c] + pos[l * Dc + c];
    g_x[(size_t)bl * Dc + c] = v;
    bf16 h = __float2bfloat16(v);
    bf16 lo = __float2bfloat16(v - __bfloat162float(h));
    bf16* oa = g_xA3 + (size_t)bl * 384 + 3*c;
    oa[0] = h; oa[1] = h; oa[2] = lo;
    bf16* ob = g_xB3 + (size_t)3 * bl * Dc + c;
    ob[0] = h; ob[Dc] = lo; ob[2*Dc] = h;
    if (c == 0) g_mask[bl] = (p < NUM_TOTAL_C) ? 0.f : -10000.f;
}

__global__ void build_c_kernel(int left, int right)
{
    int n = threadIdx.x;
    double s = 0.0;
    for (int f = left; f < right; f++) {
        double w;
        if (f == 0)           w = 1.0;
        else if (f == Lc/2)   w = (n & 1) ? -1.0 : 1.0;
        else                  w = 2.0 * cos(2.0 * M_PI * (double)f * (double)n / (double)Lc);
        s += w;
    }
    g_c[n] = (float)(s / (double)Lc);
}

__global__ void build_C3_kernel()
{
    int n = blockIdx.x, m = threadIdx.x;
    float v = g_c[(n - m + Lc) & (Lc - 1)];
    bf16 h = __float2bfloat16(v);
    bf16 l = __float2bfloat16(v - __bfloat162float(h));
    bf16* o = g_Cm3 + (size_t)n * (3*Lc) + 3*m;
    o[0] = h; o[1] = h; o[2] = l;
}

// weight rows tripled (h,l,h) — B-role NN
__global__ void conv_rows3(const float* __restrict__ in, bf16* __restrict__ out, int N)
{
    size_t idx = (size_t)blockIdx.x * 256 + threadIdx.x;
    size_t r = idx / (unsigned)N;
    int   n = (int)(idx - r * (unsigned)N);
    float v = in[idx];
    bf16 h = __float2bfloat16(v);
    bf16 l = __float2bfloat16(v - __bfloat162float(h));
    bf16* o = out + (3*r) * (size_t)N + n;
    o[0] = h; o[(size_t)N] = l; o[(size_t)2*N] = h;
}

__global__ void meanred_kernel()
{
    int b = blockIdx.x, d = threadIdx.x;
    float s = 0.f;
    #pragma unroll
    for (int p = 0; p < 8; p++) s += g_mvp[((size_t)p * Bc + b) * Lc + d];
    g_mv[b * Lc + d] = s;
}

__global__ void gmean_kernel()
{
    int d = threadIdx.x;
    float s = 0.f;
    for (int b = 0; b < Bc; b++) s += g_mv[b * Lc + d];
    g_gm[d] = s * (1.0f / (float)Bc);
}

__global__ void topk_kernel()
{
    __shared__ float sv[Lc];
    __shared__ int   si[Lc];
    int t = threadIdx.x;
    float my = g_gm[t];
    for (int it = 0; it < TOPKc; it++) {
        sv[t] = my; si[t] = t;
        __syncthreads();
        for (int s = 128; s > 0; s >>= 1) {
            if (t < s) {
                float v2 = sv[t + s]; int i2 = si[t + s];
                if (v2 > sv[t] || (v2 == sv[t] && i2 < si[t])) { sv[t] = v2; si[t] = i2; }
            }
            __syncthreads();
        }
        int win = si[0];
        if (t == 0) g_delays[it] = win;
        __syncthreads();
        if (t == win) my = -INFINITY;
    }
}

__global__ void wsoft_kernel()
{
    int b = threadIdx.x;
    float w[TOPKc];
    float mx = -1e30f;
    for (int t = 0; t < TOPKc; t++) {
        w[t] = g_mv[b * Lc + g_delays[t]];
        mx = fmaxf(mx, w[t]);
    }
    float s = 0.f;
    for (int t = 0; t < TOPKc; t++) { w[t] = expf(w[t] - mx); s += w[t]; }
    float inv = 1.0f / s;
    for (int t = 0; t < TOPKc; t++) g_w[b * TOPKc + t] = w[t] * inv;
}

// 0.9*freq + 0.1*spatial, emitted directly as A-role triple o3
__global__ void combine_kernel()
{
    int bl = blockIdx.x, c = threadIdx.x;
    int b = bl >> 8, l = bl & 255;
    __shared__ float w[TOPKc];
    __shared__ int   dl[TOPKc];
    if (c < TOPKc) { w[c] = g_w[b * TOPKc + c]; dl[c] = g_delays[c]; }
    __syncthreads();
    float f = 0.f;
    #pragma unroll
    for (int t = 0; t < TOPKc; t++) {
        int ls = (l + dl[t]) & 255;
        f += w[t] * g_vb[((size_t)b * Lc + ls) * Dc + c];
    }
    float v = 0.9f * f + 0.1f * g_sp[(size_t)bl * Dc + c];
    bf16 h = __float2bfloat16(v);
    bf16 lo = __float2bfloat16(v - __bfloat162float(h));
    bf16* o = g_o3 + (size_t)bl * 384 + 3*c;
    o[0] = h; o[1] = h; o[2] = lo;
}

__global__ void gather_kernel(const int* __restrict__ lengths, float* __restrict__ out)
{
    int b = blockIdx.x, c = threadIdx.x;
    int l = lengths[b] - 1;
    out[b * Dc + c] = g_x[((size_t)b * Lc + l) * Dc + c];
}

// ---------------- host side ----------------
static inline void mma_nn(const bf16* A, const bf16* B, float* C,
                          int M, int N, int K, int lda, int ldb, int ldc,
                          int batch, int zdiv,
                          long sA1, long sA2, long sB1, long sB2, long sC1, long sC2,
                          const float* R, int ldr, int fuse,
                          int emit, bf16* aux1, bf16* aux2)
{
    dim3 grid(M / 128, N / 128, batch);
    mma_kernel<128><<<grid, 256>>>(A, B, C, K, lda, ldb, ldc,
        zdiv, sA1, sA2, sB1, sB2, sC1, sC2, R, ldr, fuse, emit, aux1, aux2);
}

extern "C" void kernel_launch(void* const* d_in, const int* in_sizes, int n_in,
                              void* d_out, int out_size)
{
    (void)in_sizes; (void)n_in; (void)out_size;
    const int*   paths   = (const int*)  d_in[0];
    const int*   lengths = (const int*)  d_in[1];
    const float* ego     = (const float*)d_in[4];
    const float* pos     = (const float*)d_in[5];
    const float* Wq      = (const float*)d_in[6];
    const float* Wk      = (const float*)d_in[7];
    const float* Wv      = (const float*)d_in[8];
    const float* Wp      = (const float*)d_in[9];
    const float* F1      = (const float*)d_in[10];
    const float* F2      = (const float*)d_in[11];
    float* out = (float*)d_out;

    float *px, *pmask, *pvb, *psp, *pmvp;
    bf16 *pCm3, *pxA3, *pxB3, *pxtA3, *pqt3, *pkt3, *pvth, *pvtl, *po3, *pa3, *ph3, *pW3;
    cudaGetSymbolAddress((void**)&px,    g_x);
    cudaGetSymbolAddress((void**)&pmask, g_mask);
    cudaGetSymbolAddress((void**)&pvb,   g_vb);
    cudaGetSymbolAddress((void**)&psp,   g_sp);
    cudaGetSymbolAddress((void**)&pmvp,  g_mvp);
    cudaGetSymbolAddress((void**)&pCm3,  g_Cm3);
    cudaGetSymbolAddress((void**)&pxA3,  g_xA3);
    cudaGetSymbolAddress((void**)&pxB3,  g_xB3);
    cudaGetSymbolAddress((void**)&pxtA3, g_xtA3);
    cudaGetSymbolAddress((void**)&pqt3,  g_qt3);
    cudaGetSymbolAddress((void**)&pkt3,  g_kt3);
    cudaGetSymbolAddress((void**)&pvth,  g_vth);
    cudaGetSymbolAddress((void**)&pvtl,  g_vtl);
    cudaGetSymbolAddress((void**)&po3,   g_o3);
    cudaGetSymbolAddress((void**)&pa3,   g_a3);
    cudaGetSymbolAddress((void**)&ph3,   g_h3);
    cudaGetSymbolAddress((void**)&pW3,   g_W3);

    static int smem_set = 0;
    if (!smem_set) {
        cudaFuncSetAttribute(fattn_kernel,
                             cudaFuncAttributeMaxDynamicSharedMemorySize, 209920);
        smem_set = 1;
    }

    const int  BL = Bc * Lc;
    const long LD = (long)Lc * Dc;

    build_x_kernel<<<BL, Dc>>>(paths, ego, pos);

    const int lefts[NLc]  = {51, 0};
    const int rights[NLc] = {129, 78};

    for (int k = 0; k < NLc; k++) {
        build_c_kernel<<<1, Lc>>>(lefts[k], rights[k]);
        build_C3_kernel<<<Lc, Lc>>>();

        conv_rows3<<<Dc*Dc/256, 256>>>(Wq + (size_t)k*Dc*Dc, pW3 + W3_Q, Dc);
        conv_rows3<<<Dc*Dc/256, 256>>>(Wk + (size_t)k*Dc*Dc, pW3 + W3_K, Dc);
        conv_rows3<<<Dc*Dc/256, 256>>>(Wv + (size_t)k*Dc*Dc, pW3 + W3_V, Dc);
        conv_rows3<<<Dc*Dc/256, 256>>>(Wp + (size_t)k*Dc*Dc, pW3 + W3_P, Dc);
        conv_rows3<<<Dc*2*Dc/256, 256>>>(F1 + (size_t)k*Dc*2*Dc, pW3 + W3_F1, 2*Dc);
        conv_rows3<<<2*Dc*Dc/256, 256>>>(F2 + (size_t)k*2*Dc*Dc, pW3 + W3_F2, Dc);

        // xt = Cm @ x  -> emit A-role triple only (xtA3)
        mma_nn(pCm3, pxB3, psp /*dummy*/, Lc, Dc, 3*Lc, 3*Lc, Dc, Dc,
               Bc, 1, 0, 0, 3*LD, 0, LD, 0,
               nullptr, 0, 0, 2, pxtA3, nullptr);

        // vb = x @ Wv (fp32, for delay-gather)
        mma_nn(pxA3, pW3 + W3_V, pvb, BL, Dc, 3*Dc, 3*Dc, Dc, Dc,
               1, 1, 0, 0, 0, 0, 0, 0, nullptr, 0, 0, 1, nullptr, nullptr);

        // filtered projections -> attention operands, emitted as splits
        mma_nn(pxtA3, pW3 + W3_Q, psp, BL, Dc, 3*Dc, 3*Dc, Dc, Dc,
               1, 1, 0, 0, 0, 0, 0, 0, nullptr, 0, 0, 2, pqt3, nullptr);
        mma_nn(pxtA3, pW3 + W3_K, psp, BL, Dc, 3*Dc, 3*Dc, Dc, Dc,
               1, 1, 0, 0, 0, 0, 0, 0, nullptr, 0, 0, 4, pkt3, nullptr);
        mma_nn(pxtA3, pW3 + W3_V, psp, BL, Dc, 3*Dc, 3*Dc, Dc, Dc,
               1, 1, 0, 0, 0, 0, 0, 0, nullptr, 0, 0, 8, pvth, pvtl);

        // fused attention: raw S + meanv partials + softmax + P@V
        {
            dim3 grid(4, Bc * Hc);
            fattn_kernel<<<grid, 256, 209920>>>(pqt3, pkt3, pvth, pvtl,
                                                pmask, psp, pmvp);
        }
        meanred_kernel<<<Bc, Lc>>>();
        gmean_kernel<<<1, Lc>>>();
        topk_kernel<<<1, Lc>>>();
        wsoft_kernel<<<1, Bc>>>();

        combine_kernel<<<BL, Dc>>>();   // -> o3 triple

        // a = o @ Wp + x  -> a3 triple only
        mma_nn(po3, pW3 + W3_P, psp, BL, Dc, 3*Dc, 3*Dc, Dc, Dc,
               1, 1, 0, 0, 0, 0, 0, 0, px, Dc, 1, 2, pa3, nullptr);

        // h = GELU(a @ F1) -> h3 triple only
        mma_nn(pa3, pW3 + W3_F1, psp, BL, 2*Dc, 3*Dc, 3*Dc, 2*Dc, 2*Dc,
               1, 1, 0, 0, 0, 0, 0, 0, nullptr, 0, 2, 2, ph3, nullptr);

        // x = h @ F2  -> fp32 x + xA3 + xB3 (for next layer)
        mma_nn(ph3, pW3 + W3_F2, px, BL, Dc, 3*2*Dc, 3*2*Dc, Dc, Dc,
               1, 1, 0, 0, 0, 0, 0, 0, nullptr, 0, 0, 1 | 2 | 16, pxA3, pxB3);
    }

    gather_kernel<<<Bc, Dc>>>(lengths, out);
}